// round 1
// baseline (speedup 1.0000x reference)
#include <cuda_runtime.h>

#define L 4096
#define DE 1024
#define DV 1024
#define HEXP 0.2f            // hurst - 0.5
#define DTF (1.0f / 4096.0f)
#define EPSV 1e-8f

// Scratch (static device globals — allowed; no runtime allocation)
__device__ float g_Y[L * DV];   // 16 MB intermediate Y = E^T @ W^T  (L x DV)
__device__ float g_f[L];        // Toeplitz coefficients f[d]

// ---------------------------------------------------------------------------
// f[d]: d==0 -> eps^H ; d>=1 -> (d*dt + eps)^H
// ---------------------------------------------------------------------------
__global__ void compute_f_kernel() {
    int d = blockIdx.x * blockDim.x + threadIdx.x;
    if (d < L) {
        float base = (d == 0) ? EPSV : ((float)d * DTF + EPSV);
        g_f[d] = powf(base, HEXP);
    }
}

// ---------------------------------------------------------------------------
// GEMM1: Y[l,v] = sum_e E[e*L + l] * W[v*DE + e]
// 128x128 tile, BK=8, 256 threads, 8x8 per thread.
// ---------------------------------------------------------------------------
__global__ __launch_bounds__(256) void gemm1_kernel(const float* __restrict__ E,
                                                    const float* __restrict__ W) {
    __shared__ float As[8][128];       // As[e][l]
    __shared__ float Bs[8][132];       // Bs[e][v], padded to dodge transpose-store conflicts

    const int t  = threadIdx.x;
    const int tx = t & 15;             // 0..15  -> v sub-tile
    const int ty = t >> 4;             // 0..15  -> l sub-tile
    const int l0 = blockIdx.y * 128;
    const int v0 = blockIdx.x * 128;

    float acc[8][8];
    #pragma unroll
    for (int m = 0; m < 8; ++m)
        #pragma unroll
        for (int n = 0; n < 8; ++n) acc[m][n] = 0.f;

    const int er = t >> 5;             // 0..7
    const int lr = (t & 31) * 4;       // 0..124
    const int vr = t >> 1;             // 0..127
    const int ep = (t & 1) * 4;        // 0 or 4

    for (int e0 = 0; e0 < DE; e0 += 8) {
        // A tile: contiguous along l
        float4 a4 = *reinterpret_cast<const float4*>(&E[(e0 + er) * L + l0 + lr]);
        *reinterpret_cast<float4*>(&As[er][lr]) = a4;
        // B tile: contiguous along e, transpose into smem
        float4 b4 = *reinterpret_cast<const float4*>(&W[(v0 + vr) * DE + e0 + ep]);
        Bs[ep + 0][vr] = b4.x;
        Bs[ep + 1][vr] = b4.y;
        Bs[ep + 2][vr] = b4.z;
        Bs[ep + 3][vr] = b4.w;
        __syncthreads();

        #pragma unroll
        for (int k = 0; k < 8; ++k) {
            float af[8], bf[8];
            #pragma unroll
            for (int m = 0; m < 8; ++m) af[m] = As[k][ty * 8 + m];
            #pragma unroll
            for (int n = 0; n < 8; ++n) bf[n] = Bs[k][tx * 8 + n];
            #pragma unroll
            for (int m = 0; m < 8; ++m)
                #pragma unroll
                for (int n = 0; n < 8; ++n) acc[m][n] = fmaf(af[m], bf[n], acc[m][n]);
        }
        __syncthreads();
    }

    #pragma unroll
    for (int m = 0; m < 8; ++m) {
        float* row = &g_Y[(l0 + ty * 8 + m) * DV + v0 + tx * 8];
        #pragma unroll
        for (int n = 0; n < 8; n += 4) {
            float4 o = make_float4(acc[m][n], acc[m][n + 1], acc[m][n + 2], acc[m][n + 3]);
            *reinterpret_cast<float4*>(&row[n]) = o;
        }
    }
}

// ---------------------------------------------------------------------------
// GEMM2: out[i,v] = sum_{j<=i} f[i-j] * Y[j,v]
// Toeplitz lower-triangular: A tile synthesized from g_f; k-loop stops at diag.
// ---------------------------------------------------------------------------
__global__ __launch_bounds__(256) void gemm2_kernel(float* __restrict__ out) {
    __shared__ float As[8][128];       // As[j][i] = f(i-j) or 0
    __shared__ float Bs[8][128];       // Bs[j][v] = Y[j,v]

    const int t  = threadIdx.x;
    const int tx = t & 15;
    const int ty = t >> 4;
    const int i0 = blockIdx.y * 128;
    const int v0 = blockIdx.x * 128;

    float acc[8][8];
    #pragma unroll
    for (int m = 0; m < 8; ++m)
        #pragma unroll
        for (int n = 0; n < 8; ++n) acc[m][n] = 0.f;

    const int kk = t >> 5;             // 0..7  (j within tile)
    const int ir = (t & 31) * 4;       // 0..124

    const int ktiles = (i0 + 128) / 8; // j0 = kt*8 must satisfy j0 < i0+128

    for (int kt = 0; kt < ktiles; ++kt) {
        const int j0 = kt * 8;
        const int j  = j0 + kk;
        // synthesize A2 tile from f (Toeplitz)
        #pragma unroll
        for (int u = 0; u < 4; ++u) {
            int i = i0 + ir + u;
            As[kk][ir + u] = (i >= j) ? g_f[i - j] : 0.f;
        }
        // Y tile: contiguous along v
        float4 b4 = *reinterpret_cast<const float4*>(&g_Y[j * DV + v0 + ir]);
        *reinterpret_cast<float4*>(&Bs[kk][ir]) = b4;
        __syncthreads();

        #pragma unroll
        for (int k = 0; k < 8; ++k) {
            float af[8], bf[8];
            #pragma unroll
            for (int m = 0; m < 8; ++m) af[m] = As[k][ty * 8 + m];
            #pragma unroll
            for (int n = 0; n < 8; ++n) bf[n] = Bs[k][tx * 8 + n];
            #pragma unroll
            for (int m = 0; m < 8; ++m)
                #pragma unroll
                for (int n = 0; n < 8; ++n) acc[m][n] = fmaf(af[m], bf[n], acc[m][n]);
        }
        __syncthreads();
    }

    #pragma unroll
    for (int m = 0; m < 8; ++m) {
        float* row = &out[(i0 + ty * 8 + m) * DV + v0 + tx * 8];
        #pragma unroll
        for (int n = 0; n < 8; n += 4) {
            float4 o = make_float4(acc[m][n], acc[m][n + 1], acc[m][n + 2], acc[m][n + 3]);
            *reinterpret_cast<float4*>(&row[n]) = o;
        }
    }
}

// ---------------------------------------------------------------------------
extern "C" void kernel_launch(void* const* d_in, const int* in_sizes, int n_in,
                              void* d_out, int out_size) {
    const float* E = (const float*)d_in[0];   // embed_series (1024 x 4096)
    const float* W = (const float*)d_in[1];   // Wv_weight    (1024 x 1024)
    float* out = (float*)d_out;               // (4096 x 1024)

    compute_f_kernel<<<L / 256, 256>>>();
    dim3 grid1(DV / 128, L / 128);
    gemm1_kernel<<<grid1, 256>>>(E, W);
    dim3 grid2(DV / 128, L / 128);
    gemm2_kernel<<<grid2, 256>>>(out);
}

// round 3
// speedup vs baseline: 3.7403x; 3.7403x over previous
#include <cuda_runtime.h>
#include <cuda_bf16.h>
#include <cstdint>

#define L 4096
#define DE 1024
#define DV 1024
#define HEXP 0.2f
#define DTF (1.0f / 4096.0f)
#define EPSV 1e-8f

// ---------------- device scratch (static, no runtime alloc) ----------------
__device__ __nv_bfloat16 g_Et_hi[L * DE];   // E^T hi  ([l][e], e contiguous)
__device__ __nv_bfloat16 g_Et_lo[L * DE];
__device__ __nv_bfloat16 g_W_hi[DV * DE];   // W  ([v][e], e contiguous)
__device__ __nv_bfloat16 g_W_lo[DV * DE];
__device__ __nv_bfloat16 g_Yt_hi[DV * L];   // Y^T ([v][l], l contiguous)
__device__ __nv_bfloat16 g_Yt_lo[DV * L];
__device__ __nv_bfloat16 g_f_hi[L];
__device__ __nv_bfloat16 g_f_lo[L];

// ---------------- helpers ---------------------------------------------------
__device__ __forceinline__ uint32_t smem_u32(const void* p) {
    uint32_t a;
    asm("{ .reg .u64 t; cvta.to.shared.u64 t, %1; cvt.u32.u64 %0, t; }" : "=r"(a) : "l"(p));
    return a;
}
#define SW64(o) ((uint32_t)(o) ^ ((((uint32_t)(o)) >> 3) & 0x30u))

__device__ __forceinline__ void cpasync16(uint32_t dst, const void* src) {
    asm volatile("cp.async.cg.shared.global [%0], [%1], 16;" :: "r"(dst), "l"(src));
}
#define CP_COMMIT() asm volatile("cp.async.commit_group;" ::: "memory")
#define CP_WAIT2()  asm volatile("cp.async.wait_group 2;" ::: "memory")

__device__ __forceinline__ void ldsm4(uint32_t* r, uint32_t addr) {
    asm volatile("ldmatrix.sync.aligned.m8n8.x4.shared.b16 {%0,%1,%2,%3}, [%4];"
                 : "=r"(r[0]), "=r"(r[1]), "=r"(r[2]), "=r"(r[3]) : "r"(addr));
}
__device__ __forceinline__ void mma_bf16(float* c, const uint32_t* a, const uint32_t* b) {
    asm volatile(
        "mma.sync.aligned.m16n8k16.row.col.f32.bf16.bf16.f32 "
        "{%0,%1,%2,%3}, {%4,%5,%6,%7}, {%8,%9}, {%0,%1,%2,%3};"
        : "+f"(c[0]), "+f"(c[1]), "+f"(c[2]), "+f"(c[3])
        : "r"(a[0]), "r"(a[1]), "r"(a[2]), "r"(a[3]), "r"(b[0]), "r"(b[1]));
}

// ---------------- tiling constants ------------------------------------------
// CTA tile 128(m) x 128(n), BK=32, 3 stages.
// Per stage: Ahi(8K) Alo(8K) Bhi(8K) Blo(8K) = 32KB.  3 stages = 96KB.
#define STAGE_BYTES 32768
#define T_AHI 0
#define T_ALO 8192
#define T_BHI 16384
#define T_BLO 24576
#define SMEM_SZ (3 * STAGE_BYTES)

// fill one 128x32 bf16 k-major tile via cp.async (16B per thread-chunk)
__device__ __forceinline__ void fill_tile32(uint32_t dstbase,
                                            const __nv_bfloat16* __restrict__ g,
                                            int row0, int k0, int stride, int tid) {
#pragma unroll
    for (int i = 0; i < 2; ++i) {
        int q = tid + i * 256;
        int r = q >> 2, c = q & 3;
        uint32_t o = (uint32_t)(r * 64 + c * 16);
        cpasync16(dstbase + SW64(o), g + (size_t)(row0 + r) * stride + k0 + c * 8);
    }
}

// fill 128x32 Toeplitz tiles (hi+lo) with regular stores
__device__ __forceinline__ void fill_toep32(char* smemc, uint32_t off_hi, uint32_t off_lo,
                                            int i0, int j0, int tid) {
#pragma unroll
    for (int i = 0; i < 2; ++i) {
        int q = tid + i * 256;
        int r = q >> 2, c = q & 3;
        int ii = i0 + r, jj = j0 + c * 8;
        alignas(16) __nv_bfloat16 vh[8];
        alignas(16) __nv_bfloat16 vl[8];
#pragma unroll
        for (int u = 0; u < 8; ++u) {
            int d = ii - (jj + u);
            bool ok = (d >= 0);
            vh[u] = ok ? g_f_hi[d] : __float2bfloat16(0.0f);
            vl[u] = ok ? g_f_lo[d] : __float2bfloat16(0.0f);
        }
        uint32_t so = SW64((uint32_t)(r * 64 + c * 16));
        *reinterpret_cast<uint4*>(smemc + off_hi + so) = *reinterpret_cast<uint4*>(vh);
        *reinterpret_cast<uint4*>(smemc + off_lo + so) = *reinterpret_cast<uint4*>(vl);
    }
}

// ---------------- pre-kernels -----------------------------------------------
__global__ void compute_f_kernel() {
    int d = blockIdx.x * blockDim.x + threadIdx.x;
    if (d < L) {
        float base = (d == 0) ? EPSV : ((float)d * DTF + EPSV);
        float v = powf(base, HEXP);
        __nv_bfloat16 hi = __float2bfloat16(v);
        g_f_hi[d] = hi;
        g_f_lo[d] = __float2bfloat16(v - __bfloat162float(hi));
    }
}

__global__ void transpose_E_kernel(const float* __restrict__ E) {
    __shared__ float t[32][33];
    int bx = blockIdx.x, by = blockIdx.y;
    int tx = threadIdx.x, ty = threadIdx.y;      // block (32, 8)
#pragma unroll
    for (int i = 0; i < 4; ++i)
        t[ty + 8 * i][tx] = E[(size_t)(by * 32 + ty + 8 * i) * L + bx * 32 + tx];
    __syncthreads();
#pragma unroll
    for (int i = 0; i < 4; ++i) {
        float v = t[tx][ty + 8 * i];
        size_t o = (size_t)(bx * 32 + ty + 8 * i) * DE + by * 32 + tx;
        __nv_bfloat16 hi = __float2bfloat16(v);
        g_Et_hi[o] = hi;
        g_Et_lo[o] = __float2bfloat16(v - __bfloat162float(hi));
    }
}

__global__ void convert_W_kernel(const float* __restrict__ W) {
    int i = blockIdx.x * blockDim.x + threadIdx.x;
#pragma unroll
    for (int u = 0; u < 4; ++u) {
        int idx = i * 4 + u;
        float v = W[idx];
        __nv_bfloat16 hi = __float2bfloat16(v);
        g_W_hi[idx] = hi;
        g_W_lo[idx] = __float2bfloat16(v - __bfloat162float(hi));
    }
}

// ---------------- shared compute core ---------------------------------------
// acc layout: acc[mi][ni][4]; warp tile 64(m) x 32(n); wm = wid&1, wn = wid>>2? no:
// 8 warps: wm = wid & 1 (2 x 64 rows), wn = wid >> 1 (4 x 32 cols).
struct Frag { float a[4][4][4]; };

__device__ __forceinline__ void compute_stage(uint32_t sbase, int lane, int wm, int wn,
                                              float acc[4][4][4]) {
    // per-lane ldmatrix byte offsets (kk = 0)
    const int arow = lane & 15;
    const int acolb = (lane >> 4) << 4;                       // 0 or 16 bytes
    const int brow = (lane & 7) + ((lane >> 4) << 3);         // 0..15
    const int bcolb = ((lane >> 3) & 1) << 4;                 // 0 or 16 bytes
#pragma unroll
    for (int kk = 0; kk < 2; ++kk) {
        uint32_t aH[4][4], aL[4][4], bH[2][4], bL[2][4];
#pragma unroll
        for (int mi = 0; mi < 4; ++mi) {
            uint32_t o = SW64((uint32_t)((wm * 64 + mi * 16 + arow) * 64 + acolb)) ^ (kk << 5);
            ldsm4(aH[mi], sbase + T_AHI + o);
            ldsm4(aL[mi], sbase + T_ALO + o);
        }
#pragma unroll
        for (int pi = 0; pi < 2; ++pi) {
            uint32_t o = SW64((uint32_t)((wn * 32 + pi * 16 + brow) * 64 + bcolb)) ^ (kk << 5);
            ldsm4(bH[pi], sbase + T_BHI + o);
            ldsm4(bL[pi], sbase + T_BLO + o);
        }
#pragma unroll
        for (int mi = 0; mi < 4; ++mi)
#pragma unroll
            for (int ni = 0; ni < 4; ++ni) {
                const uint32_t* bh = &bH[ni >> 1][(ni & 1) * 2];
                const uint32_t* bl = &bL[ni >> 1][(ni & 1) * 2];
                mma_bf16(acc[mi][ni], aH[mi], bh);
                mma_bf16(acc[mi][ni], aH[mi], bl);
                mma_bf16(acc[mi][ni], aL[mi], bh);
            }
    }
}

// ---------------- GEMM1: Yt[v][l] = sum_e W[v][e] * Et[l][e] ----------------
// m = v (A = W), n = l (B = Et), k = e.
__global__ __launch_bounds__(256) void gemm1_mma() {
    extern __shared__ char smem[];
    const uint32_t sb = smem_u32(smem);
    const int tid = threadIdx.x, lane = tid & 31, wid = tid >> 5;
    const int wm = wid & 1, wn = wid >> 1;
    const int l0 = blockIdx.x * 128;   // n
    const int v0 = blockIdx.y * 128;   // m
    const int KT = DE / 32;

    float acc[4][4][4];
#pragma unroll
    for (int mi = 0; mi < 4; ++mi)
#pragma unroll
        for (int ni = 0; ni < 4; ++ni)
#pragma unroll
            for (int r = 0; r < 4; ++r) acc[mi][ni][r] = 0.f;

    // prologue: stages 0,1
#pragma unroll
    for (int s = 0; s < 2; ++s) {
        uint32_t st = sb + s * STAGE_BYTES;
        int k0 = s * 32;
        fill_tile32(st + T_AHI, g_W_hi, v0, k0, DE, tid);
        fill_tile32(st + T_ALO, g_W_lo, v0, k0, DE, tid);
        fill_tile32(st + T_BHI, g_Et_hi, l0, k0, DE, tid);
        fill_tile32(st + T_BLO, g_Et_lo, l0, k0, DE, tid);
        CP_COMMIT();
    }
    for (int kt = 0; kt < KT; ++kt) {
        int ls = kt + 2;
        if (ls < KT) {
            uint32_t st = sb + (ls % 3) * STAGE_BYTES;
            int k0 = ls * 32;
            fill_tile32(st + T_AHI, g_W_hi, v0, k0, DE, tid);
            fill_tile32(st + T_ALO, g_W_lo, v0, k0, DE, tid);
            fill_tile32(st + T_BHI, g_Et_hi, l0, k0, DE, tid);
            fill_tile32(st + T_BLO, g_Et_lo, l0, k0, DE, tid);
        }
        CP_COMMIT();
        CP_WAIT2();
        __syncthreads();
        compute_stage(sb + (kt % 3) * STAGE_BYTES, lane, wm, wn, acc);
        __syncthreads();
    }

    // epilogue: D[m=v][n=l] -> Yt hi/lo
#pragma unroll
    for (int mi = 0; mi < 4; ++mi)
#pragma unroll
        for (int ni = 0; ni < 4; ++ni) {
            const float* c = acc[mi][ni];
            int v_ = v0 + wm * 64 + mi * 16 + (lane >> 2);
            int l_ = l0 + wn * 32 + ni * 8 + 2 * (lane & 3);
#pragma unroll
            for (int h = 0; h < 2; ++h) {
                int vv = v_ + 8 * h;
                float x0 = c[2 * h], x1 = c[2 * h + 1];
                __nv_bfloat16 h0 = __float2bfloat16(x0);
                __nv_bfloat16 h1 = __float2bfloat16(x1);
                __nv_bfloat162 hp; hp.x = h0; hp.y = h1;
                __nv_bfloat162 lp;
                lp.x = __float2bfloat16(x0 - __bfloat162float(h0));
                lp.y = __float2bfloat16(x1 - __bfloat162float(h1));
                size_t off = (size_t)vv * L + l_;
                *reinterpret_cast<__nv_bfloat162*>(&g_Yt_hi[off]) = hp;
                *reinterpret_cast<__nv_bfloat162*>(&g_Yt_lo[off]) = lp;
            }
        }
}

// ---------------- GEMM2: out[i][v] = sum_{j<=i} T[i][j] * Yt[v][j] ----------
// m = i (A = Toeplitz), n = v (B = Yt), k = j.  Triangular k-loop.
__global__ __launch_bounds__(256) void gemm2_mma(float* __restrict__ out) {
    extern __shared__ char smem[];
    const uint32_t sb = smem_u32(smem);
    const int tid = threadIdx.x, lane = tid & 31, wid = tid >> 5;
    const int wm = wid & 1, wn = wid >> 1;
    const int byy = (int)gridDim.y - 1 - (int)blockIdx.y;   // heavy tiles first
    const int i0 = byy * 128;          // m
    const int v0 = blockIdx.x * 128;   // n
    const int KT = 4 * (byy + 1);      // j tiles up to diagonal

    float acc[4][4][4];
#pragma unroll
    for (int mi = 0; mi < 4; ++mi)
#pragma unroll
        for (int ni = 0; ni < 4; ++ni)
#pragma unroll
            for (int r = 0; r < 4; ++r) acc[mi][ni][r] = 0.f;

#pragma unroll
    for (int s = 0; s < 2; ++s) {
        uint32_t st = sb + s * STAGE_BYTES;
        int j0 = s * 32;
        fill_toep32(smem + (size_t)(s * STAGE_BYTES), T_AHI, T_ALO, i0, j0, tid);
        fill_tile32(st + T_BHI, g_Yt_hi, v0, j0, L, tid);
        fill_tile32(st + T_BLO, g_Yt_lo, v0, j0, L, tid);
        CP_COMMIT();
    }
    for (int kt = 0; kt < KT; ++kt) {
        int ls = kt + 2;
        if (ls < KT) {
            int s = ls % 3;
            uint32_t st = sb + s * STAGE_BYTES;
            int j0 = ls * 32;
            fill_toep32(smem + (size_t)(s * STAGE_BYTES), T_AHI, T_ALO, i0, j0, tid);
            fill_tile32(st + T_BHI, g_Yt_hi, v0, j0, L, tid);
            fill_tile32(st + T_BLO, g_Yt_lo, v0, j0, L, tid);
        }
        CP_COMMIT();
        CP_WAIT2();
        __syncthreads();
        compute_stage(sb + (kt % 3) * STAGE_BYTES, lane, wm, wn, acc);
        __syncthreads();
    }

    // epilogue: D[m=i][n=v] -> out[i*DV + v], float2 stores
#pragma unroll
    for (int mi = 0; mi < 4; ++mi)
#pragma unroll
        for (int ni = 0; ni < 4; ++ni) {
            const float* c = acc[mi][ni];
            int i_ = i0 + wm * 64 + mi * 16 + (lane >> 2);
            int v_ = v0 + wn * 32 + ni * 8 + 2 * (lane & 3);
#pragma unroll
            for (int h = 0; h < 2; ++h) {
                float2 p;
                p.x = c[2 * h];
                p.y = c[2 * h + 1];
                *reinterpret_cast<float2*>(&out[(size_t)(i_ + 8 * h) * DV + v_]) = p;
            }
        }
}

// ---------------------------------------------------------------------------
extern "C" void kernel_launch(void* const* d_in, const int* in_sizes, int n_in,
                              void* d_out, int out_size) {
    const float* E = (const float*)d_in[0];   // (1024, 4096)
    const float* W = (const float*)d_in[1];   // (1024, 1024)
    float* out = (float*)d_out;               // (4096, 1024)

    cudaFuncSetAttribute(gemm1_mma, cudaFuncAttributeMaxDynamicSharedMemorySize, SMEM_SZ);
    cudaFuncSetAttribute(gemm2_mma, cudaFuncAttributeMaxDynamicSharedMemorySize, SMEM_SZ);

    compute_f_kernel<<<L / 256, 256>>>();
    transpose_E_kernel<<<dim3(L / 32, DE / 32), dim3(32, 8)>>>(E);
    convert_W_kernel<<<(DV * DE) / 1024, 256>>>(W);
    gemm1_mma<<<dim3(L / 128, DV / 128), 256, SMEM_SZ>>>();
    gemm2_mma<<<dim3(DV / 128, L / 128), 256, SMEM_SZ>>>(out);
}

// round 4
// speedup vs baseline: 5.1189x; 1.3686x over previous
#include <cuda_runtime.h>
#include <cuda_bf16.h>
#include <cstdint>

#define L 4096
#define DE 1024
#define DV 1024
#define HEXP 0.2f
#define DTF (1.0f / 4096.0f)
#define EPSV 1e-8f
#define FFT_N 8192

// ---------------- device scratch (static, no runtime alloc) ----------------
__device__ __nv_bfloat16 g_Et_hi[L * DE];   // E^T hi  ([l][e], e contiguous)
__device__ __nv_bfloat16 g_Et_lo[L * DE];
__device__ __nv_bfloat16 g_W_hi[DV * DE];   // W  ([v][e], e contiguous)
__device__ __nv_bfloat16 g_W_lo[DV * DE];
__device__ float g_Yt[(size_t)DV * L];      // Y^T fp32 ([v][l], l contiguous)
__device__ float g_outT[(size_t)DV * L];    // conv result [c][i]
__device__ float2 g_tw[FFT_N / 2];          // exp(-2*pi*i*n/N)
__device__ float2 g_F[FFT_N];               // FFT(f_padded)/N

// ---------------- helpers ---------------------------------------------------
__device__ __forceinline__ uint32_t smem_u32(const void* p) {
    uint32_t a;
    asm("{ .reg .u64 t; cvta.to.shared.u64 t, %1; cvt.u32.u64 %0, t; }" : "=r"(a) : "l"(p));
    return a;
}
#define SW64(o) ((uint32_t)(o) ^ ((((uint32_t)(o)) >> 3) & 0x30u))

__device__ __forceinline__ void cpasync16(uint32_t dst, const void* src) {
    asm volatile("cp.async.cg.shared.global [%0], [%1], 16;" :: "r"(dst), "l"(src));
}
#define CP_COMMIT() asm volatile("cp.async.commit_group;" ::: "memory")
#define CP_WAIT2()  asm volatile("cp.async.wait_group 2;" ::: "memory")

__device__ __forceinline__ void ldsm4(uint32_t* r, uint32_t addr) {
    asm volatile("ldmatrix.sync.aligned.m8n8.x4.shared.b16 {%0,%1,%2,%3}, [%4];"
                 : "=r"(r[0]), "=r"(r[1]), "=r"(r[2]), "=r"(r[3]) : "r"(addr));
}
__device__ __forceinline__ void mma_bf16(float* c, const uint32_t* a, const uint32_t* b) {
    asm volatile(
        "mma.sync.aligned.m16n8k16.row.col.f32.bf16.bf16.f32 "
        "{%0,%1,%2,%3}, {%4,%5,%6,%7}, {%8,%9}, {%0,%1,%2,%3};"
        : "+f"(c[0]), "+f"(c[1]), "+f"(c[2]), "+f"(c[3])
        : "r"(a[0]), "r"(a[1]), "r"(a[2]), "r"(a[3]), "r"(b[0]), "r"(b[1]));
}

// ---------------- GEMM tiling constants -------------------------------------
#define STAGE_BYTES 32768
#define T_AHI 0
#define T_ALO 8192
#define T_BHI 16384
#define T_BLO 24576
#define GEMM_SMEM (3 * STAGE_BYTES)

__device__ __forceinline__ void fill_tile32(uint32_t dstbase,
                                            const __nv_bfloat16* __restrict__ g,
                                            int row0, int k0, int stride, int tid) {
#pragma unroll
    for (int i = 0; i < 2; ++i) {
        int q = tid + i * 256;
        int r = q >> 2, c = q & 3;
        uint32_t o = (uint32_t)(r * 64 + c * 16);
        cpasync16(dstbase + SW64(o), g + (size_t)(row0 + r) * stride + k0 + c * 8);
    }
}

// ---------------- pre-kernels -----------------------------------------------
__global__ void init_tw_kernel() {
    int n = blockIdx.x * 256 + threadIdx.x;
    if (n < FFT_N / 2) {
        float s, c;
        sincospif(-(float)n / (float)(FFT_N / 2), &s, &c);
        g_tw[n] = make_float2(c, s);
    }
}

__global__ void transpose_E_kernel(const float* __restrict__ E) {
    __shared__ float t[32][33];
    int bx = blockIdx.x, by = blockIdx.y;
    int tx = threadIdx.x, ty = threadIdx.y;      // block (32, 8)
#pragma unroll
    for (int i = 0; i < 4; ++i)
        t[ty + 8 * i][tx] = E[(size_t)(by * 32 + ty + 8 * i) * L + bx * 32 + tx];
    __syncthreads();
#pragma unroll
    for (int i = 0; i < 4; ++i) {
        float v = t[tx][ty + 8 * i];
        size_t o = (size_t)(bx * 32 + ty + 8 * i) * DE + by * 32 + tx;
        __nv_bfloat16 hi = __float2bfloat16(v);
        g_Et_hi[o] = hi;
        g_Et_lo[o] = __float2bfloat16(v - __bfloat162float(hi));
    }
}

__global__ void convert_W_kernel(const float* __restrict__ W) {
    int i = blockIdx.x * blockDim.x + threadIdx.x;
#pragma unroll
    for (int u = 0; u < 4; ++u) {
        int idx = i * 4 + u;
        float v = W[idx];
        __nv_bfloat16 hi = __float2bfloat16(v);
        g_W_hi[idx] = hi;
        g_W_lo[idx] = __float2bfloat16(v - __bfloat162float(hi));
    }
}

// ---------------- radix-2 Stockham FFT on smem ping-pong ---------------------
// 13 stages; reads src0 first; result lands in dst0 (odd #stages).
// One __syncthreads per stage.
__device__ __forceinline__ void fft_stages(float2* src0, float2* dst0, int tid, int inv) {
    float2* src = src0;
    float2* dst = dst0;
#pragma unroll 1
    for (int s = 0; s < 13; ++s) {
        const int m = 1 << s;
#pragma unroll
        for (int it = 0; it < 16; ++it) {
            int bf = tid + (it << 8);
            int k = bf & (m - 1);
            int jm = bf - k;                 // j*m
            float2 a = src[bf];
            float2 b = src[bf + FFT_N / 2];
            float2 w = g_tw[jm];
            float wy = inv ? -w.y : w.y;
            float2 sum = make_float2(a.x + b.x, a.y + b.y);
            float2 dif = make_float2(a.x - b.x, a.y - b.y);
            float2 wd = make_float2(w.x * dif.x - wy * dif.y,
                                    w.x * dif.y + wy * dif.x);
            dst[bf + jm] = sum;
            dst[bf + jm + m] = wd;
        }
        __syncthreads();
        float2* t = src; src = dst; dst = t;
    }
}

// F = FFT(f_padded) / N   (single CTA)
__global__ __launch_bounds__(256) void fft_F_kernel() {
    extern __shared__ float2 sm[];
    float2* A = sm;
    float2* B = sm + FFT_N;
    int tid = threadIdx.x;
#pragma unroll
    for (int it = 0; it < 32; ++it) {
        int d = tid + it * 256;
        float v = 0.f;
        if (d < L) {
            float base = (d == 0) ? EPSV : ((float)d * DTF + EPSV);
            v = powf(base, HEXP);
        }
        A[d] = make_float2(v, 0.f);
    }
    __syncthreads();
    fft_stages(A, B, tid, 0);
    const float scale = 1.0f / (float)FFT_N;
#pragma unroll
    for (int it = 0; it < 32; ++it) {
        int n = tid + it * 256;
        g_F[n] = make_float2(B[n].x * scale, B[n].y * scale);
    }
}

// Causal conv via FFT: channels (2c, 2c+1) packed as Re/Im of one complex seq.
__global__ __launch_bounds__(256) void conv_kernel() {
    extern __shared__ float2 sm[];
    float2* A = sm;
    float2* B = sm + FFT_N;
    int tid = threadIdx.x;
    int c2 = blockIdx.x * 2;
    const float* ya = g_Yt + (size_t)c2 * L;
    const float* yb = g_Yt + (size_t)(c2 + 1) * L;
#pragma unroll
    for (int it = 0; it < 16; ++it) {
        int i = tid + it * 256;
        A[i] = make_float2(ya[i], yb[i]);
    }
#pragma unroll
    for (int it = 0; it < 16; ++it) {
        int i = L + tid + it * 256;
        A[i] = make_float2(0.f, 0.f);
    }
    __syncthreads();
    fft_stages(A, B, tid, 0);          // forward, result in B
#pragma unroll
    for (int it = 0; it < 32; ++it) {  // pointwise multiply by F (same-thread indices)
        int n = tid + it * 256;
        float2 z = B[n];
        float2 F = g_F[n];
        B[n] = make_float2(z.x * F.x - z.y * F.y, z.x * F.y + z.y * F.x);
    }
    __syncthreads();
    fft_stages(B, A, tid, 1);          // inverse (unscaled; 1/N folded into F), result in A
    float* oa = g_outT + (size_t)c2 * L;
    float* ob = g_outT + (size_t)(c2 + 1) * L;
#pragma unroll
    for (int it = 0; it < 16; ++it) {
        int i = tid + it * 256;
        float2 z = A[i];
        oa[i] = z.x;
        ob[i] = z.y;
    }
}

// g_outT [c][i] -> out [i][c]
__global__ void transpose_out_kernel(float* __restrict__ out) {
    __shared__ float t[32][33];
    int i0 = blockIdx.x * 32, c0 = blockIdx.y * 32;
    int tx = threadIdx.x, ty = threadIdx.y;  // (32, 8)
#pragma unroll
    for (int k = 0; k < 4; ++k)
        t[ty + 8 * k][tx] = g_outT[(size_t)(c0 + ty + 8 * k) * L + i0 + tx];
    __syncthreads();
#pragma unroll
    for (int k = 0; k < 4; ++k)
        out[(size_t)(i0 + ty + 8 * k) * DV + c0 + tx] = t[tx][ty + 8 * k];
}

// ---------------- GEMM1 compute core ----------------------------------------
__device__ __forceinline__ void compute_stage(uint32_t sbase, int lane, int wm, int wn,
                                              float acc[4][4][4]) {
    const int arow = lane & 15;
    const int acolb = (lane >> 4) << 4;
    const int brow = (lane & 7) + ((lane >> 4) << 3);
    const int bcolb = ((lane >> 3) & 1) << 4;
#pragma unroll
    for (int kk = 0; kk < 2; ++kk) {
        uint32_t aH[4][4], aL[4][4], bH[2][4], bL[2][4];
#pragma unroll
        for (int mi = 0; mi < 4; ++mi) {
            uint32_t o = SW64((uint32_t)((wm * 64 + mi * 16 + arow) * 64 + acolb)) ^ (kk << 5);
            ldsm4(aH[mi], sbase + T_AHI + o);
            ldsm4(aL[mi], sbase + T_ALO + o);
        }
#pragma unroll
        for (int pi = 0; pi < 2; ++pi) {
            uint32_t o = SW64((uint32_t)((wn * 32 + pi * 16 + brow) * 64 + bcolb)) ^ (kk << 5);
            ldsm4(bH[pi], sbase + T_BHI + o);
            ldsm4(bL[pi], sbase + T_BLO + o);
        }
#pragma unroll
        for (int mi = 0; mi < 4; ++mi)
#pragma unroll
            for (int ni = 0; ni < 4; ++ni) {
                const uint32_t* bh = &bH[ni >> 1][(ni & 1) * 2];
                const uint32_t* bl = &bL[ni >> 1][(ni & 1) * 2];
                mma_bf16(acc[mi][ni], aH[mi], bh);
                mma_bf16(acc[mi][ni], aH[mi], bl);
                mma_bf16(acc[mi][ni], aL[mi], bh);
            }
    }
}

// ---------------- GEMM1: Yt[v][l] = sum_e W[v][e] * Et[l][e] ----------------
__global__ __launch_bounds__(256) void gemm1_mma() {
    extern __shared__ char smem[];
    const uint32_t sb = smem_u32(smem);
    const int tid = threadIdx.x, lane = tid & 31, wid = tid >> 5;
    const int wm = wid & 1, wn = wid >> 1;
    const int l0 = blockIdx.x * 128;   // n
    const int v0 = blockIdx.y * 128;   // m
    const int KT = DE / 32;

    float acc[4][4][4];
#pragma unroll
    for (int mi = 0; mi < 4; ++mi)
#pragma unroll
        for (int ni = 0; ni < 4; ++ni)
#pragma unroll
            for (int r = 0; r < 4; ++r) acc[mi][ni][r] = 0.f;

#pragma unroll
    for (int s = 0; s < 2; ++s) {
        uint32_t st = sb + s * STAGE_BYTES;
        int k0 = s * 32;
        fill_tile32(st + T_AHI, g_W_hi, v0, k0, DE, tid);
        fill_tile32(st + T_ALO, g_W_lo, v0, k0, DE, tid);
        fill_tile32(st + T_BHI, g_Et_hi, l0, k0, DE, tid);
        fill_tile32(st + T_BLO, g_Et_lo, l0, k0, DE, tid);
        CP_COMMIT();
    }
    for (int kt = 0; kt < KT; ++kt) {
        int ls = kt + 2;
        if (ls < KT) {
            uint32_t st = sb + (ls % 3) * STAGE_BYTES;
            int k0 = ls * 32;
            fill_tile32(st + T_AHI, g_W_hi, v0, k0, DE, tid);
            fill_tile32(st + T_ALO, g_W_lo, v0, k0, DE, tid);
            fill_tile32(st + T_BHI, g_Et_hi, l0, k0, DE, tid);
            fill_tile32(st + T_BLO, g_Et_lo, l0, k0, DE, tid);
        }
        CP_COMMIT();
        CP_WAIT2();
        __syncthreads();
        compute_stage(sb + (kt % 3) * STAGE_BYTES, lane, wm, wn, acc);
        __syncthreads();
    }

    // epilogue: D[m=v][n=l] -> g_Yt fp32
#pragma unroll
    for (int mi = 0; mi < 4; ++mi)
#pragma unroll
        for (int ni = 0; ni < 4; ++ni) {
            const float* c = acc[mi][ni];
            int v_ = v0 + wm * 64 + mi * 16 + (lane >> 2);
            int l_ = l0 + wn * 32 + ni * 8 + 2 * (lane & 3);
#pragma unroll
            for (int h = 0; h < 2; ++h) {
                float2 p;
                p.x = c[2 * h];
                p.y = c[2 * h + 1];
                *reinterpret_cast<float2*>(&g_Yt[(size_t)(v_ + 8 * h) * L + l_]) = p;
            }
        }
}

// ---------------------------------------------------------------------------
#define FFT_SMEM (2 * FFT_N * (int)sizeof(float2))

extern "C" void kernel_launch(void* const* d_in, const int* in_sizes, int n_in,
                              void* d_out, int out_size) {
    const float* E = (const float*)d_in[0];   // (1024, 4096)
    const float* W = (const float*)d_in[1];   // (1024, 1024)
    float* out = (float*)d_out;               // (4096, 1024)

    cudaFuncSetAttribute(gemm1_mma, cudaFuncAttributeMaxDynamicSharedMemorySize, GEMM_SMEM);
    cudaFuncSetAttribute(fft_F_kernel, cudaFuncAttributeMaxDynamicSharedMemorySize, FFT_SMEM);
    cudaFuncSetAttribute(conv_kernel, cudaFuncAttributeMaxDynamicSharedMemorySize, FFT_SMEM);

    init_tw_kernel<<<FFT_N / 2 / 256, 256>>>();
    fft_F_kernel<<<1, 256, FFT_SMEM>>>();
    transpose_E_kernel<<<dim3(L / 32, DE / 32), dim3(32, 8)>>>(E);
    convert_W_kernel<<<(DV * DE) / 1024, 256>>>(W);
    gemm1_mma<<<dim3(L / 128, DV / 128), 256, GEMM_SMEM>>>();
    conv_kernel<<<DV / 2, 256, FFT_SMEM>>>();
    transpose_out_kernel<<<dim3(L / 32, DV / 32), dim3(32, 8)>>>(out);
}

// round 5
// speedup vs baseline: 5.9719x; 1.1666x over previous
#include <cuda_runtime.h>
#include <cuda_bf16.h>
#include <cstdint>

#define L 4096
#define DE 1024
#define DV 1024
#define HEXP 0.2f
#define DTF (1.0f / 4096.0f)
#define EPSV 1e-8f
#define FFT_N 8192

// ---------------- device scratch (static, no runtime alloc) ----------------
__device__ __nv_bfloat16 g_Et_hi[L * DE];   // E^T hi  ([l][e], e contiguous)
__device__ __nv_bfloat16 g_Et_lo[L * DE];
__device__ __nv_bfloat16 g_W_hi[DV * DE];   // W  ([v][e], e contiguous)
__device__ __nv_bfloat16 g_W_lo[DV * DE];
__device__ float g_Yt[(size_t)DV * L];      // Y^T fp32 ([v][l], l contiguous)
__device__ float g_outT[(size_t)DV * L];    // conv result [c][i]
__device__ float2 g_tw[FFT_N];              // exp(-2*pi*i*n/N), full table (for W^{3u})
__device__ float2 g_F[FFT_N];               // FFT(f_padded)/N

// ---------------- helpers ---------------------------------------------------
__device__ __forceinline__ uint32_t smem_u32(const void* p) {
    uint32_t a;
    asm("{ .reg .u64 t; cvta.to.shared.u64 t, %1; cvt.u32.u64 %0, t; }" : "=r"(a) : "l"(p));
    return a;
}
#define SW64(o) ((uint32_t)(o) ^ ((((uint32_t)(o)) >> 3) & 0x30u))

__device__ __forceinline__ void cpasync16(uint32_t dst, const void* src) {
    asm volatile("cp.async.cg.shared.global [%0], [%1], 16;" :: "r"(dst), "l"(src));
}
#define CP_COMMIT() asm volatile("cp.async.commit_group;" ::: "memory")
#define CP_WAIT2()  asm volatile("cp.async.wait_group 2;" ::: "memory")

__device__ __forceinline__ void ldsm4(uint32_t* r, uint32_t addr) {
    asm volatile("ldmatrix.sync.aligned.m8n8.x4.shared.b16 {%0,%1,%2,%3}, [%4];"
                 : "=r"(r[0]), "=r"(r[1]), "=r"(r[2]), "=r"(r[3]) : "r"(addr));
}
__device__ __forceinline__ void mma_bf16(float* c, const uint32_t* a, const uint32_t* b) {
    asm volatile(
        "mma.sync.aligned.m16n8k16.row.col.f32.bf16.bf16.f32 "
        "{%0,%1,%2,%3}, {%4,%5,%6,%7}, {%8,%9}, {%0,%1,%2,%3};"
        : "+f"(c[0]), "+f"(c[1]), "+f"(c[2]), "+f"(c[3])
        : "r"(a[0]), "r"(a[1]), "r"(a[2]), "r"(a[3]), "r"(b[0]), "r"(b[1]));
}

__device__ __forceinline__ float2 cmul(float2 a, float2 b) {
    return make_float2(a.x * b.x - a.y * b.y, a.x * b.y + a.y * b.x);
}
__device__ __forceinline__ float2 cadd(float2 a, float2 b) { return make_float2(a.x + b.x, a.y + b.y); }
__device__ __forceinline__ float2 csub(float2 a, float2 b) { return make_float2(a.x - b.x, a.y - b.y); }

// ---------------- GEMM tiling constants -------------------------------------
#define STAGE_BYTES 32768
#define T_AHI 0
#define T_ALO 8192
#define T_BHI 16384
#define T_BLO 24576
#define GEMM_SMEM (3 * STAGE_BYTES)

__device__ __forceinline__ void fill_tile32(uint32_t dstbase,
                                            const __nv_bfloat16* __restrict__ g,
                                            int row0, int k0, int stride, int tid) {
#pragma unroll
    for (int i = 0; i < 2; ++i) {
        int q = tid + i * 256;
        int r = q >> 2, c = q & 3;
        uint32_t o = (uint32_t)(r * 64 + c * 16);
        cpasync16(dstbase + SW64(o), g + (size_t)(row0 + r) * stride + k0 + c * 8);
    }
}

// ---------------- pre-kernels -----------------------------------------------
__global__ void init_tw_kernel() {
    int n = blockIdx.x * 256 + threadIdx.x;
    if (n < FFT_N) {
        float s, c;
        sincospif(-2.0f * (float)n / (float)FFT_N, &s, &c);
        g_tw[n] = make_float2(c, s);
    }
}

__global__ void transpose_E_kernel(const float* __restrict__ E) {
    __shared__ float t[32][33];
    int bx = blockIdx.x, by = blockIdx.y;
    int tx = threadIdx.x, ty = threadIdx.y;      // block (32, 8)
#pragma unroll
    for (int i = 0; i < 4; ++i)
        t[ty + 8 * i][tx] = E[(size_t)(by * 32 + ty + 8 * i) * L + bx * 32 + tx];
    __syncthreads();
#pragma unroll
    for (int i = 0; i < 4; ++i) {
        float v = t[tx][ty + 8 * i];
        size_t o = (size_t)(bx * 32 + ty + 8 * i) * DE + by * 32 + tx;
        __nv_bfloat16 hi = __float2bfloat16(v);
        g_Et_hi[o] = hi;
        g_Et_lo[o] = __float2bfloat16(v - __bfloat162float(hi));
    }
}

__global__ void convert_W_kernel(const float* __restrict__ W) {
    int i = blockIdx.x * blockDim.x + threadIdx.x;
#pragma unroll
    for (int u = 0; u < 4; ++u) {
        int idx = i * 4 + u;
        float v = W[idx];
        __nv_bfloat16 hi = __float2bfloat16(v);
        g_W_hi[idx] = hi;
        g_W_lo[idx] = __float2bfloat16(v - __bfloat162float(hi));
    }
}

// ---------------- radix-4 Stockham FFT (6 r4 stages + 1 r2 stage) ------------
// Reads src0; result lands in dst0 after 7 stage-passes.
__device__ __forceinline__ void fft_stages4(float2* src0, float2* dst0, int tid, int inv) {
    float2* src = src0;
    float2* dst = dst0;
    int m = 1;
#pragma unroll 1
    for (int s = 0; s < 6; ++s) {
#pragma unroll
        for (int it = 0; it < 8; ++it) {
            int bf = tid + (it << 8);            // 0..2047
            int k = bf & (m - 1);
            int u = bf - k;                      // q*m
            float2 x0 = src[bf];
            float2 x1 = src[bf + FFT_N / 4];
            float2 x2 = src[bf + FFT_N / 2];
            float2 x3 = src[bf + 3 * (FFT_N / 4)];
            float2 t0 = cadd(x0, x2);
            float2 t1 = csub(x0, x2);
            float2 t2 = cadd(x1, x3);
            float2 t3 = csub(x1, x3);
            // jt3 = (-i*t3) fwd, (+i*t3) inv
            float2 jt3 = inv ? make_float2(-t3.y, t3.x) : make_float2(t3.y, -t3.x);
            float2 w1 = g_tw[u];
            float2 w2 = g_tw[2 * u];
            float2 w3 = g_tw[3 * u];
            if (inv) { w1.y = -w1.y; w2.y = -w2.y; w3.y = -w3.y; }
            int b4 = 4 * u + k;
            dst[b4]         = cadd(t0, t2);
            dst[b4 + m]     = cmul(w1, cadd(t1, jt3));
            dst[b4 + 2 * m] = cmul(w2, csub(t0, t2));
            dst[b4 + 3 * m] = cmul(w3, csub(t1, jt3));
        }
        __syncthreads();
        float2* t = src; src = dst; dst = t;
        m <<= 2;
    }
    // final radix-2 stage: m = 4096, q = 0, twiddle = 1
#pragma unroll
    for (int it = 0; it < 16; ++it) {
        int k = tid + (it << 8);                 // 0..4095
        float2 a = src[k];
        float2 b = src[k + FFT_N / 2];
        dst[k] = cadd(a, b);
        dst[k + FFT_N / 2] = csub(a, b);
    }
    __syncthreads();
}

// F = FFT(f_padded) / N   (single CTA)
__global__ __launch_bounds__(256) void fft_F_kernel() {
    extern __shared__ float2 sm[];
    float2* A = sm;
    float2* B = sm + FFT_N;
    int tid = threadIdx.x;
#pragma unroll
    for (int it = 0; it < 32; ++it) {
        int d = tid + it * 256;
        float v = 0.f;
        if (d < L) {
            float base = (d == 0) ? EPSV : ((float)d * DTF + EPSV);
            v = powf(base, HEXP);
        }
        A[d] = make_float2(v, 0.f);
    }
    __syncthreads();
    fft_stages4(A, B, tid, 0);
    const float scale = 1.0f / (float)FFT_N;
#pragma unroll
    for (int it = 0; it < 32; ++it) {
        int n = tid + it * 256;
        g_F[n] = make_float2(B[n].x * scale, B[n].y * scale);
    }
}

// Causal conv via FFT: channels (2c, 2c+1) packed as Re/Im of one complex seq.
__global__ __launch_bounds__(256) void conv_kernel() {
    extern __shared__ float2 sm[];
    float2* A = sm;
    float2* B = sm + FFT_N;
    int tid = threadIdx.x;
    int c2 = blockIdx.x * 2;
    const float* ya = g_Yt + (size_t)c2 * L;
    const float* yb = g_Yt + (size_t)(c2 + 1) * L;
#pragma unroll
    for (int it = 0; it < 16; ++it) {
        int i = tid + it * 256;
        A[i] = make_float2(ya[i], yb[i]);
    }
#pragma unroll
    for (int it = 0; it < 16; ++it) {
        int i = L + tid + it * 256;
        A[i] = make_float2(0.f, 0.f);
    }
    __syncthreads();
    fft_stages4(A, B, tid, 0);         // forward, result in B
#pragma unroll
    for (int it = 0; it < 32; ++it) {  // pointwise multiply by F
        int n = tid + it * 256;
        B[n] = cmul(B[n], g_F[n]);
    }
    __syncthreads();
    fft_stages4(B, A, tid, 1);         // inverse (1/N folded into F), result in A
    float* oa = g_outT + (size_t)c2 * L;
    float* ob = g_outT + (size_t)(c2 + 1) * L;
#pragma unroll
    for (int it = 0; it < 16; ++it) {
        int i = tid + it * 256;
        float2 z = A[i];
        oa[i] = z.x;
        ob[i] = z.y;
    }
}

// g_outT [c][i] -> out [i][c]
__global__ void transpose_out_kernel(float* __restrict__ out) {
    __shared__ float t[32][33];
    int i0 = blockIdx.x * 32, c0 = blockIdx.y * 32;
    int tx = threadIdx.x, ty = threadIdx.y;  // (32, 8)
#pragma unroll
    for (int k = 0; k < 4; ++k)
        t[ty + 8 * k][tx] = g_outT[(size_t)(c0 + ty + 8 * k) * L + i0 + tx];
    __syncthreads();
#pragma unroll
    for (int k = 0; k < 4; ++k)
        out[(size_t)(i0 + ty + 8 * k) * DV + c0 + tx] = t[tx][ty + 8 * k];
}

// ---------------- GEMM1 compute core ----------------------------------------
__device__ __forceinline__ void compute_stage(uint32_t sbase, int lane, int wm, int wn,
                                              float acc[4][4][4]) {
    const int arow = lane & 15;
    const int acolb = (lane >> 4) << 4;
    const int brow = (lane & 7) + ((lane >> 4) << 3);
    const int bcolb = ((lane >> 3) & 1) << 4;
#pragma unroll
    for (int kk = 0; kk < 2; ++kk) {
        uint32_t aH[4][4], aL[4][4], bH[2][4], bL[2][4];
#pragma unroll
        for (int mi = 0; mi < 4; ++mi) {
            uint32_t o = SW64((uint32_t)((wm * 64 + mi * 16 + arow) * 64 + acolb)) ^ (kk << 5);
            ldsm4(aH[mi], sbase + T_AHI + o);
            ldsm4(aL[mi], sbase + T_ALO + o);
        }
#pragma unroll
        for (int pi = 0; pi < 2; ++pi) {
            uint32_t o = SW64((uint32_t)((wn * 32 + pi * 16 + brow) * 64 + bcolb)) ^ (kk << 5);
            ldsm4(bH[pi], sbase + T_BHI + o);
            ldsm4(bL[pi], sbase + T_BLO + o);
        }
#pragma unroll
        for (int mi = 0; mi < 4; ++mi)
#pragma unroll
            for (int ni = 0; ni < 4; ++ni) {
                const uint32_t* bh = &bH[ni >> 1][(ni & 1) * 2];
                const uint32_t* bl = &bL[ni >> 1][(ni & 1) * 2];
                mma_bf16(acc[mi][ni], aH[mi], bh);
                mma_bf16(acc[mi][ni], aH[mi], bl);
                mma_bf16(acc[mi][ni], aL[mi], bh);
            }
    }
}

// ---------------- GEMM1: Yt[v][l] = sum_e W[v][e] * Et[l][e] ----------------
__global__ __launch_bounds__(256) void gemm1_mma() {
    extern __shared__ char smem[];
    const uint32_t sb = smem_u32(smem);
    const int tid = threadIdx.x, lane = tid & 31, wid = tid >> 5;
    const int wm = wid & 1, wn = wid >> 1;
    const int l0 = blockIdx.x * 128;   // n
    const int v0 = blockIdx.y * 128;   // m
    const int KT = DE / 32;

    float acc[4][4][4];
#pragma unroll
    for (int mi = 0; mi < 4; ++mi)
#pragma unroll
        for (int ni = 0; ni < 4; ++ni)
#pragma unroll
            for (int r = 0; r < 4; ++r) acc[mi][ni][r] = 0.f;

#pragma unroll
    for (int s = 0; s < 2; ++s) {
        uint32_t st = sb + s * STAGE_BYTES;
        int k0 = s * 32;
        fill_tile32(st + T_AHI, g_W_hi, v0, k0, DE, tid);
        fill_tile32(st + T_ALO, g_W_lo, v0, k0, DE, tid);
        fill_tile32(st + T_BHI, g_Et_hi, l0, k0, DE, tid);
        fill_tile32(st + T_BLO, g_Et_lo, l0, k0, DE, tid);
        CP_COMMIT();
    }
    for (int kt = 0; kt < KT; ++kt) {
        int ls = kt + 2;
        if (ls < KT) {
            uint32_t st = sb + (ls % 3) * STAGE_BYTES;
            int k0 = ls * 32;
            fill_tile32(st + T_AHI, g_W_hi, v0, k0, DE, tid);
            fill_tile32(st + T_ALO, g_W_lo, v0, k0, DE, tid);
            fill_tile32(st + T_BHI, g_Et_hi, l0, k0, DE, tid);
            fill_tile32(st + T_BLO, g_Et_lo, l0, k0, DE, tid);
        }
        CP_COMMIT();
        CP_WAIT2();
        __syncthreads();
        compute_stage(sb + (kt % 3) * STAGE_BYTES, lane, wm, wn, acc);
        __syncthreads();
    }

    // epilogue: D[m=v][n=l] -> g_Yt fp32
#pragma unroll
    for (int mi = 0; mi < 4; ++mi)
#pragma unroll
        for (int ni = 0; ni < 4; ++ni) {
            const float* c = acc[mi][ni];
            int v_ = v0 + wm * 64 + mi * 16 + (lane >> 2);
            int l_ = l0 + wn * 32 + ni * 8 + 2 * (lane & 3);
#pragma unroll
            for (int h = 0; h < 2; ++h) {
                float2 p;
                p.x = c[2 * h];
                p.y = c[2 * h + 1];
                *reinterpret_cast<float2*>(&g_Yt[(size_t)(v_ + 8 * h) * L + l_]) = p;
            }
        }
}

// ---------------------------------------------------------------------------
#define FFT_SMEM (2 * FFT_N * (int)sizeof(float2))

extern "C" void kernel_launch(void* const* d_in, const int* in_sizes, int n_in,
                              void* d_out, int out_size) {
    const float* E = (const float*)d_in[0];   // (1024, 4096)
    const float* W = (const float*)d_in[1];   // (1024, 1024)
    float* out = (float*)d_out;               // (4096, 1024)

    cudaFuncSetAttribute(gemm1_mma, cudaFuncAttributeMaxDynamicSharedMemorySize, GEMM_SMEM);
    cudaFuncSetAttribute(fft_F_kernel, cudaFuncAttributeMaxDynamicSharedMemorySize, FFT_SMEM);
    cudaFuncSetAttribute(conv_kernel, cudaFuncAttributeMaxDynamicSharedMemorySize, FFT_SMEM);

    init_tw_kernel<<<FFT_N / 256, 256>>>();
    fft_F_kernel<<<1, 256, FFT_SMEM>>>();
    transpose_E_kernel<<<dim3(L / 32, DE / 32), dim3(32, 8)>>>(E);
    convert_W_kernel<<<(DV * DE) / 1024, 256>>>(W);
    gemm1_mma<<<dim3(L / 128, DV / 128), 256, GEMM_SMEM>>>();
    conv_kernel<<<DV / 2, 256, FFT_SMEM>>>();
    transpose_out_kernel<<<dim3(L / 32, DV / 32), dim3(32, 8)>>>(out);
}